// round 2
// baseline (speedup 1.0000x reference)
#include <cuda_runtime.h>
#include <utility>

using ull = unsigned long long;

namespace tp {

constexpr int LMAX = 4;
constexpr int NM   = 25;    // (L+1)^2
constexpr int NB   = 128;
constexpr int NC   = 128;
constexpr int NC2  = NC / 2;     // 64 f32x2 lanes per b
constexpr int MAXNNZ = 8192;

constexpr int iabs(int v) { return v < 0 ? -v : v; }

struct Pat {
  int nnz;
  short seg[MAXNNZ];
  short m1[MAXNNZ];
  short m2[MAXNNZ];
};

// Replicates reference _build_cg_pattern() INCLUDING the sort:
// iteration order (l_out,m_out)->(l1,m1)->(l2,m2) is lexicographic in
// (seg, M1, M2) because seg = l(l+1)+m is monotone in (l, m).
constexpr Pat build_pat() {
  Pat p{};
  int n = 0;
  for (int lo = 0; lo <= LMAX; ++lo)
    for (int mo = -lo; mo <= lo; ++mo)
      for (int l1 = 0; l1 <= LMAX; ++l1)
        for (int u1 = -l1; u1 <= l1; ++u1)
          for (int l2 = 0; l2 <= LMAX; ++l2) {
            if (l2 < iabs(lo - l1) || l2 > lo + l1) continue;
            for (int u2 = -l2; u2 <= l2; ++u2) {
              if (iabs(u1 + u2) == iabs(mo) || iabs(u1 - u2) == iabs(mo)) {
                p.seg[n] = (short)(lo * (lo + 1) + mo);
                p.m1 [n] = (short)(l1 * (l1 + 1) + u1);
                p.m2 [n] = (short)(l2 * (l2 + 1) + u2);
                ++n;
              }
            }
          }
  p.nnz = n;
  return p;
}

constexpr Pat PAT = build_pat();
constexpr int NNZ = PAT.nnz;          // scalar read: folds fine in device code
static_assert(NNZ > 0 && NNZ < MAXNNZ, "nnz bounds");

constexpr int NG = 4;  // entry groups per block (each owns disjoint output segs)

struct Splits { int e[NG + 1]; int mlo[NG]; int mhi[NG]; };

constexpr Splits build_splits() {
  Splits s{};
  int segstart[NM + 1] = {};
  for (int m = 0; m <= NM; ++m) {
    int i = 0;
    while (i < NNZ && PAT.seg[i] < m) ++i;
    segstart[m] = i;
  }
  s.e[0] = 0; s.e[NG] = NNZ;
  for (int g = 1; g < NG; ++g) {
    int target = (NNZ * g) / NG;
    int best = 0, bd = 1 << 30;
    for (int m = 0; m <= NM; ++m) {
      int d = segstart[m] - target; if (d < 0) d = -d;
      if (d < bd) { bd = d; best = segstart[m]; }
    }
    s.e[g] = best;
  }
  for (int g = 0; g < NG; ++g) {
    s.mlo[g] = (s.e[g]     < NNZ) ? (int)PAT.seg[s.e[g]]     : NM;
    s.mhi[g] = (s.e[g + 1] < NNZ) ? (int)PAT.seg[s.e[g + 1]] : NM;
  }
  return s;
}

constexpr Splits SPL = build_splits();

// ---- packed f32x2 math (sm_103a; ptxas never emits these from C++) ----
__device__ __forceinline__ ull mul2(ull a, ull b) {
  ull r;
  asm("mul.rn.f32x2 %0, %1, %2;" : "=l"(r) : "l"(a), "l"(b));
  return r;
}
__device__ __forceinline__ void fma2(ull& d, ull a, ull b) {
  asm("fma.rn.f32x2 %0, %1, %2, %3;" : "=l"(d) : "l"(a), "l"(b), "l"(d));
}

// One CG entry. SEG/A/B2/J arrive as template arguments (literals by the time
// this body is compiled for device), so the host constexpr tables are never
// odr-used in device code. Identical mul2(x1r[A], x2r[B2]) across entries of
// one (M1,M2) pair CSE at the SASS level (asm is non-volatile).
template<int SEG, int A, int B2, int J>
__device__ __forceinline__ void ent(ull* __restrict__ acc,
                                    const ull* __restrict__ x1r,
                                    const ull* __restrict__ x2r,
                                    const ull* __restrict__ scg) {
  fma2(acc[SEG], scg[J], mul2(x1r[A], x2r[B2]));
}

template<int E0, int... I>
__device__ __forceinline__ void accum_impl(ull* __restrict__ acc,
                                           const ull* __restrict__ x1r,
                                           const ull* __restrict__ x2r,
                                           const ull* __restrict__ scg,
                                           std::integer_sequence<int, I...>) {
  // PAT accesses below are in template-argument position: evaluated at
  // instantiation time, never referenced from device code.
  ( ent<PAT.seg[E0 + I], PAT.m1[E0 + I], PAT.m2[E0 + I], I>(acc, x1r, x2r, scg),
    ... );
}

template<int E0, int E1, int MLO, int MHI>
__device__ __forceinline__ void run_group(const ull* __restrict__ x1u,
                                          const ull* __restrict__ x2u,
                                          ull* __restrict__ outu,
                                          const ull* __restrict__ scg,
                                          int c2) {
  ull x1r[NM], x2r[NM];
#pragma unroll
  for (int m = 0; m < NM; ++m) {
    x1r[m] = x1u[m * NC2 + c2];
    x2r[m] = x2u[m * NC2 + c2];
  }
  ull acc[NM];
#pragma unroll
  for (int s = MLO; s < MHI; ++s) acc[s] = 0ull;

  accum_impl<E0>(acc, x1r, x2r, scg + E0,
                 std::make_integer_sequence<int, E1 - E0>{});

#pragma unroll
  for (int s = MLO; s < MHI; ++s) outu[s * NC2 + c2] = acc[s];
}

__global__ void __launch_bounds__(NG * NC2, 1)
tp_kernel(const float* __restrict__ x1, const float* __restrict__ x2,
          const float* __restrict__ cg, float* __restrict__ out) {
  __shared__ __align__(16) ull scg[NNZ];   // cg duplicated into both f32x2 lanes
  const int tid = threadIdx.x;
  for (int i = tid; i < NNZ; i += NG * NC2) {
    ull u = (ull)__float_as_uint(cg[i]);
    scg[i] = u | (u << 32);
  }
  __syncthreads();

  const int b  = blockIdx.x;
  const int c2 = tid & (NC2 - 1);
  const int g  = tid >> 6;

  const ull* x1u = reinterpret_cast<const ull*>(x1) + b * (NM * NC2);
  const ull* x2u = reinterpret_cast<const ull*>(x2) + b * (NM * NC2);
  ull*       ou  = reinterpret_cast<ull*>(out)      + b * (NM * NC2);

  // SPL accesses are template arguments -> compile-time literals.
  switch (g) {
    case 0: run_group<SPL.e[0], SPL.e[1], SPL.mlo[0], SPL.mhi[0]>(x1u, x2u, ou, scg, c2); break;
    case 1: run_group<SPL.e[1], SPL.e[2], SPL.mlo[1], SPL.mhi[1]>(x1u, x2u, ou, scg, c2); break;
    case 2: run_group<SPL.e[2], SPL.e[3], SPL.mlo[2], SPL.mhi[2]>(x1u, x2u, ou, scg, c2); break;
    case 3: run_group<SPL.e[3], SPL.e[4], SPL.mlo[3], SPL.mhi[3]>(x1u, x2u, ou, scg, c2); break;
  }
}

// ---- generic fallback (only if runtime nnz != compile-time NNZ) ----
__global__ void tp_generic(const float* __restrict__ x1, const float* __restrict__ x2,
                           const float* __restrict__ cg,
                           const int* __restrict__ M1, const int* __restrict__ M2,
                           const int* __restrict__ seg, int nnz,
                           float* __restrict__ out) {
  const int b = blockIdx.x;
  const int c = threadIdx.x;
  const float* x1b = x1 + b * NM * NC;
  const float* x2b = x2 + b * NM * NC;
  float acc = 0.f;
  int cur = seg[0];
  for (int i = 0; i < nnz; ++i) {
    int s = seg[i];
    if (s != cur) { out[(b * NM + cur) * NC + c] = acc; acc = 0.f; cur = s; }
    acc += cg[i] * x1b[M1[i] * NC + c] * x2b[M2[i] * NC + c];
  }
  out[(b * NM + cur) * NC + c] = acc;
}

}  // namespace tp

extern "C" void kernel_launch(void* const* d_in, const int* in_sizes, int n_in,
                              void* d_out, int out_size) {
  const float* x1 = (const float*)d_in[0];
  const float* x2 = (const float*)d_in[1];
  const float* cg = (const float*)d_in[2];
  const int*   M1 = (const int*)  d_in[3];
  const int*   M2 = (const int*)  d_in[4];
  const int*   sg = (const int*)  d_in[5];
  float* out = (float*)d_out;

  if (in_sizes[2] == tp::NNZ) {
    tp::tp_kernel<<<tp::NB, tp::NG * tp::NC2>>>(x1, x2, cg, out);
  } else {
    // pattern mismatch safety net: zero then generic runtime-indexed kernel
    cudaMemsetAsync(d_out, 0, (size_t)out_size * sizeof(float));
    tp::tp_generic<<<tp::NB, tp::NC>>>(x1, x2, cg, M1, M2, sg, in_sizes[2], out);
  }
}

// round 4
// speedup vs baseline: 1.2117x; 1.2117x over previous
#include <cuda_runtime.h>
#include <utility>

using ull = unsigned long long;

namespace tp {

constexpr int LMAX = 4;
constexpr int NM   = 25;    // (L+1)^2
constexpr int NB   = 128;
constexpr int NC   = 128;
constexpr int NCU  = NC / 2;     // 64 f32x2 (ull) elements per (b, m) row
constexpr int MAXNNZ = 8192;

constexpr int iabs(int v) { return v < 0 ? -v : v; }

struct Pat {
  int nnz;
  short seg[MAXNNZ];
  short m1[MAXNNZ];
  short m2[MAXNNZ];
};

// Replicates reference _build_cg_pattern() INCLUDING the sort:
// iteration order (l_out,m_out)->(l1,m1)->(l2,m2) is lexicographic in
// (seg, M1, M2) because seg = l(l+1)+m is monotone in (l, m).
constexpr Pat build_pat() {
  Pat p{};
  int n = 0;
  for (int lo = 0; lo <= LMAX; ++lo)
    for (int mo = -lo; mo <= lo; ++mo)
      for (int l1 = 0; l1 <= LMAX; ++l1)
        for (int u1 = -l1; u1 <= l1; ++u1)
          for (int l2 = 0; l2 <= LMAX; ++l2) {
            if (l2 < iabs(lo - l1) || l2 > lo + l1) continue;
            for (int u2 = -l2; u2 <= l2; ++u2) {
              if (iabs(u1 + u2) == iabs(mo) || iabs(u1 - u2) == iabs(mo)) {
                p.seg[n] = (short)(lo * (lo + 1) + mo);
                p.m1 [n] = (short)(l1 * (l1 + 1) + u1);
                p.m2 [n] = (short)(l2 * (l2 + 1) + u2);
                ++n;
              }
            }
          }
  p.nnz = n;
  return p;
}

constexpr Pat PAT = build_pat();
constexpr int NNZ = PAT.nnz;
static_assert(NNZ > 0 && NNZ < MAXNNZ, "nnz bounds");

constexpr int NG = 8;  // one warp per group

// Pair-organized execution plan: per group, unique (m1,m2) pairs; each pair
// carries the list of (seg, cg-index) FMAs that consume its product.
struct Plan {
  int e[NG + 1];                 // entry ranges (at segment boundaries)
  int mlo[NG], mhi[NG];          // output segment range per group
  unsigned u1[NG], u2[NG];       // usage bitmasks over m1 / m2 (25 bits)
  int pbase[NG + 1];             // pair offsets per group
  short pm1[MAXNNZ], pm2[MAXNNZ];
  int fbase[MAXNNZ + 1];         // fma offsets per pair
  short fseg[MAXNNZ];            // output segment of each fma
  short fcgi[MAXNNZ];            // absolute cg index of each fma
};

// O(nnz) via counting sort over pair-id = m1*25+m2 (625 bins per group).
// Stays far under nvcc's constexpr step limit (the R3 version was O(nnz^2)).
constexpr Plan build_plan() {
  Plan s{};
  int segstart[NM + 1] = {};
  {
    int pos = 0;
    for (int m = 0; m <= NM; ++m) {
      while (pos < NNZ && PAT.seg[pos] < m) ++pos;
      segstart[m] = pos;
    }
  }
  s.e[0] = 0; s.e[NG] = NNZ;
  for (int g = 1; g < NG; ++g) {
    int target = (NNZ * g) / NG;
    int best = 0, bd = 1 << 30;
    for (int m = 0; m <= NM; ++m) {
      int d = segstart[m] - target; if (d < 0) d = -d;
      if (d < bd) { bd = d; best = segstart[m]; }
    }
    s.e[g] = best;
  }
  int np = 0, nf = 0;
  for (int g = 0; g < NG; ++g) {
    const int e0 = s.e[g], e1 = s.e[g + 1];
    s.mlo[g] = (e0 < NNZ) ? (int)PAT.seg[e0] : NM;
    s.mhi[g] = (e1 < NNZ) ? (int)PAT.seg[e1] : NM;
    s.pbase[g] = np;
    unsigned u1 = 0, u2 = 0;
    int cnt[NM * NM] = {};
    for (int j = e0; j < e1; ++j) {
      u1 |= 1u << PAT.m1[j];
      u2 |= 1u << PAT.m2[j];
      cnt[PAT.m1[j] * NM + PAT.m2[j]]++;
    }
    int off[NM * NM] = {};
    for (int pid = 0; pid < NM * NM; ++pid) {
      if (cnt[pid]) {
        s.pm1[np] = (short)(pid / NM);
        s.pm2[np] = (short)(pid % NM);
        s.fbase[np] = nf;
        off[pid] = nf;
        nf += cnt[pid];
        ++np;
      }
    }
    for (int j = e0; j < e1; ++j) {
      int pid = PAT.m1[j] * NM + PAT.m2[j];
      s.fseg[off[pid]] = PAT.seg[j];
      s.fcgi[off[pid]] = (short)j;
      off[pid]++;
    }
    s.u1[g] = u1; s.u2[g] = u2;
  }
  s.pbase[NG] = np;
  s.fbase[np] = nf;
  return s;
}

constexpr Plan PLAN = build_plan();

// ---- packed f32x2 math (sm_103a; ptxas never emits these from C++) ----
__device__ __forceinline__ ull mul2(ull a, ull b) {
  ull r;
  asm("mul.rn.f32x2 %0, %1, %2;" : "=l"(r) : "l"(a), "l"(b));
  return r;
}
__device__ __forceinline__ void fma2(ull& d, ull a, ull b) {
  asm("fma.rn.f32x2 %0, %1, %2, %3;" : "=l"(d) : "l"(a), "l"(b), "l"(d));
}

// All PLAN/PAT reads below appear ONLY in template-argument position, so they
// are resolved at instantiation time and never odr-used from device code.

template<int ACCI, int CGI>
__device__ __forceinline__ void fop(ull* __restrict__ acc,
                                    const ull* __restrict__ scg, ull p) {
  fma2(acc[ACCI], scg[CGI], p);   // LDS.64 [scg + literal] broadcast
}

template<int M1v, int M2v, int MLO, int FB, int... FI>
__device__ __forceinline__ void pair_run(ull* __restrict__ acc,
                                         const ull* __restrict__ x1r,
                                         const ull* __restrict__ x2r,
                                         const ull* __restrict__ scg,
                                         std::integer_sequence<int, FI...>) {
  ull p = mul2(x1r[M1v], x2r[M2v]);   // product used immediately (short live range)
  ( fop<PLAN.fseg[FB + FI] - MLO, PLAN.fcgi[FB + FI]>(acc, scg, p), ... );
}

template<int MLO, int PB, int... PI>
__device__ __forceinline__ void group_run(ull* __restrict__ acc,
                                          const ull* __restrict__ x1r,
                                          const ull* __restrict__ x2r,
                                          const ull* __restrict__ scg,
                                          std::integer_sequence<int, PI...>) {
  ( pair_run<PLAN.pm1[PB + PI], PLAN.pm2[PB + PI], MLO, PLAN.fbase[PB + PI]>(
        acc, x1r, x2r, scg,
        std::make_integer_sequence<int, PLAN.fbase[PB + PI + 1] - PLAN.fbase[PB + PI]>{}),
    ... );
}

template<unsigned MASK, int M>
__device__ __forceinline__ void load1(ull* __restrict__ r,
                                      const ull* __restrict__ src, int c) {
  if constexpr ((MASK >> M) & 1u) r[M] = src[M * NCU + c];
}
template<unsigned MASK, int... M>
__device__ __forceinline__ void loadm(ull* __restrict__ r,
                                      const ull* __restrict__ src, int c,
                                      std::integer_sequence<int, M...>) {
  ( load1<MASK, M>(r, src, c), ... );
}

template<int MLO, int... S>
__device__ __forceinline__ void storem(ull* __restrict__ outu,
                                       const ull* __restrict__ acc, int c,
                                       std::integer_sequence<int, S...>) {
  ( (outu[(MLO + S) * NCU + c] = acc[S]), ... );
}

template<int MLO, int MHI, int PB, int PE, unsigned U1, unsigned U2>
__device__ __forceinline__ void rg(const ull* __restrict__ x1u,
                                   const ull* __restrict__ x2u,
                                   ull* __restrict__ outu,
                                   const ull* __restrict__ scg, int c) {
  ull x1r[NM], x2r[NM];
  loadm<U1>(x1r, x1u, c, std::make_integer_sequence<int, NM>{});
  loadm<U2>(x2r, x2u, c, std::make_integer_sequence<int, NM>{});
  ull acc[MHI - MLO] = {};
  group_run<MLO, PB>(acc, x1r, x2r, scg,
                     std::make_integer_sequence<int, PE - PB>{});
  storem<MLO>(outu, acc, c, std::make_integer_sequence<int, MHI - MLO>{});
}

template<int G>
__device__ __forceinline__ void rung(const ull* __restrict__ x1u,
                                     const ull* __restrict__ x2u,
                                     ull* __restrict__ outu,
                                     const ull* __restrict__ scg, int c) {
  rg<PLAN.mlo[G], PLAN.mhi[G], PLAN.pbase[G], PLAN.pbase[G + 1],
     PLAN.u1[G], PLAN.u2[G]>(x1u, x2u, outu, scg, c);
}

__global__ void __launch_bounds__(256, 2)
tp_kernel(const float* __restrict__ x1, const float* __restrict__ x2,
          const float* __restrict__ cg, float* __restrict__ out) {
  __shared__ __align__(16) ull scg[NNZ];   // cg duplicated into both f32x2 lanes
  const int tid = threadIdx.x;
  for (int i = tid; i < NNZ; i += 256) {
    ull u = (ull)__float_as_uint(__ldg(cg + i));
    scg[i] = u | (u << 32);
  }
  __syncthreads();

  const int bx = blockIdx.x;
  const int b  = bx & (NB - 1);
  const int h  = bx >> 7;                  // channel half
  const int c  = h * 32 + (tid & 31);      // f32x2 lane index within row
  const int g  = tid >> 5;                 // one warp == one group

  const ull* x1u = reinterpret_cast<const ull*>(x1) + b * (NM * NCU);
  const ull* x2u = reinterpret_cast<const ull*>(x2) + b * (NM * NCU);
  ull*       ou  = reinterpret_cast<ull*>(out)      + b * (NM * NCU);

  switch (g) {
    case 0: rung<0>(x1u, x2u, ou, scg, c); break;
    case 1: rung<1>(x1u, x2u, ou, scg, c); break;
    case 2: rung<2>(x1u, x2u, ou, scg, c); break;
    case 3: rung<3>(x1u, x2u, ou, scg, c); break;
    case 4: rung<4>(x1u, x2u, ou, scg, c); break;
    case 5: rung<5>(x1u, x2u, ou, scg, c); break;
    case 6: rung<6>(x1u, x2u, ou, scg, c); break;
    case 7: rung<7>(x1u, x2u, ou, scg, c); break;
  }
}

// ---- generic fallback (only if runtime nnz != compile-time NNZ) ----
__global__ void tp_generic(const float* __restrict__ x1, const float* __restrict__ x2,
                           const float* __restrict__ cg,
                           const int* __restrict__ M1, const int* __restrict__ M2,
                           const int* __restrict__ seg, int nnz,
                           float* __restrict__ out) {
  const int b = blockIdx.x;
  const int c = threadIdx.x;
  const float* x1b = x1 + b * NM * NC;
  const float* x2b = x2 + b * NM * NC;
  float acc = 0.f;
  int cur = seg[0];
  for (int i = 0; i < nnz; ++i) {
    int s = seg[i];
    if (s != cur) { out[(b * NM + cur) * NC + c] = acc; acc = 0.f; cur = s; }
    acc += cg[i] * x1b[M1[i] * NC + c] * x2b[M2[i] * NC + c];
  }
  out[(b * NM + cur) * NC + c] = acc;
}

}  // namespace tp

extern "C" void kernel_launch(void* const* d_in, const int* in_sizes, int n_in,
                              void* d_out, int out_size) {
  const float* x1 = (const float*)d_in[0];
  const float* x2 = (const float*)d_in[1];
  const float* cg = (const float*)d_in[2];
  const int*   M1 = (const int*)  d_in[3];
  const int*   M2 = (const int*)  d_in[4];
  const int*   sg = (const int*)  d_in[5];
  float* out = (float*)d_out;

  if (in_sizes[2] == tp::NNZ) {
    tp::tp_kernel<<<2 * tp::NB, 256>>>(x1, x2, cg, out);
  } else {
    // pattern mismatch safety net: zero then generic runtime-indexed kernel
    cudaMemsetAsync(d_out, 0, (size_t)out_size * sizeof(float));
    tp::tp_generic<<<tp::NB, tp::NC>>>(x1, x2, cg, M1, M2, sg, in_sizes[2], out);
  }
}

// round 6
// speedup vs baseline: 1.4938x; 1.2328x over previous
#include <cuda_runtime.h>
#include <utility>

using ull = unsigned long long;

namespace tp {

constexpr int LMAX = 4;
constexpr int NM   = 25;    // (L+1)^2
constexpr int NB   = 128;
constexpr int NC   = 128;
constexpr int NCU  = NC / 2;     // 64 f32x2 (ull) elements per (b, m) row
constexpr int MAXNNZ = 8192;

constexpr int iabs(int v) { return v < 0 ? -v : v; }

struct Pat {
  int nnz;
  short seg[MAXNNZ];
  short m1[MAXNNZ];
  short m2[MAXNNZ];
};

// Replicates reference _build_cg_pattern() INCLUDING the sort:
// iteration order (l_out,m_out)->(l1,m1)->(l2,m2) is lexicographic in
// (seg, M1, M2) because seg = l(l+1)+m is monotone in (l, m).
constexpr Pat build_pat() {
  Pat p{};
  int n = 0;
  for (int lo = 0; lo <= LMAX; ++lo)
    for (int mo = -lo; mo <= lo; ++mo)
      for (int l1 = 0; l1 <= LMAX; ++l1)
        for (int u1 = -l1; u1 <= l1; ++u1)
          for (int l2 = 0; l2 <= LMAX; ++l2) {
            if (l2 < iabs(lo - l1) || l2 > lo + l1) continue;
            for (int u2 = -l2; u2 <= l2; ++u2) {
              if (iabs(u1 + u2) == iabs(mo) || iabs(u1 - u2) == iabs(mo)) {
                p.seg[n] = (short)(lo * (lo + 1) + mo);
                p.m1 [n] = (short)(l1 * (l1 + 1) + u1);
                p.m2 [n] = (short)(l2 * (l2 + 1) + u2);
                ++n;
              }
            }
          }
  p.nnz = n;
  return p;
}

constexpr Pat PAT = build_pat();
constexpr int NNZ = PAT.nnz;
static_assert(NNZ > 0 && NNZ < MAXNNZ, "nnz bounds");

constexpr int NG    = 8;   // segment groups (one warp per group per channel-half)
constexpr int CHUNK = 8;   // cg values prefetched per FMA-chunk

// Flattened pair-major execution plan. FMAs of one (m1,m2) pair are
// consecutive; the first carries the product computation. Same evaluation
// order as R4 (counting-sort pair order) -> bitwise-identical accumulation.
struct Plan {
  int e[NG + 1];
  int mlo[NG], mhi[NG];
  unsigned u1[NG], u2[NG];       // usage bitmasks over m1 / m2
  int fb[NG + 1];                // flat fma ranges per group
  short fseg[MAXNNZ];            // output segment (absolute)
  short fm1[MAXNNZ], fm2[MAXNNZ];
  short ffirst[MAXNNZ];          // 1 = first fma of its pair (compute product)
  short fcgi[MAXNNZ];            // smem cg index (original entry index)
};

// O(nnz) counting sort over pair-id = m1*25+m2 per group.
constexpr Plan build_plan() {
  Plan s{};
  int segstart[NM + 1] = {};
  {
    int pos = 0;
    for (int m = 0; m <= NM; ++m) {
      while (pos < NNZ && PAT.seg[pos] < m) ++pos;
      segstart[m] = pos;
    }
  }
  s.e[0] = 0; s.e[NG] = NNZ;
  for (int g = 1; g < NG; ++g) {
    int target = (NNZ * g) / NG;
    int best = 0, bd = 1 << 30;
    for (int m = 0; m <= NM; ++m) {
      int d = segstart[m] - target; if (d < 0) d = -d;
      if (d < bd) { bd = d; best = segstart[m]; }
    }
    s.e[g] = best;
  }
  int nf = 0;
  for (int g = 0; g < NG; ++g) {
    const int e0 = s.e[g], e1 = s.e[g + 1];
    s.mlo[g] = (e0 < NNZ) ? (int)PAT.seg[e0] : NM;
    s.mhi[g] = (e1 < NNZ) ? (int)PAT.seg[e1] : NM;
    s.fb[g] = nf;
    unsigned u1 = 0, u2 = 0;
    int cnt[NM * NM] = {};
    for (int j = e0; j < e1; ++j) {
      u1 |= 1u << PAT.m1[j];
      u2 |= 1u << PAT.m2[j];
      cnt[PAT.m1[j] * NM + PAT.m2[j]]++;
    }
    int off[NM * NM] = {};
    int base[NM * NM] = {};
    for (int pid = 0; pid < NM * NM; ++pid) {
      if (cnt[pid]) { off[pid] = nf; base[pid] = nf; nf += cnt[pid]; }
    }
    for (int j = e0; j < e1; ++j) {
      int pid = PAT.m1[j] * NM + PAT.m2[j];
      int pos = off[pid]++;
      s.fseg[pos]  = PAT.seg[j];
      s.fm1[pos]   = PAT.m1[j];
      s.fm2[pos]   = PAT.m2[j];
      s.fcgi[pos]  = (short)j;
      s.ffirst[pos] = (short)(pos == base[pid]);
    }
    s.u1[g] = u1; s.u2[g] = u2;
  }
  s.fb[NG] = nf;
  return s;
}

constexpr Plan PLAN = build_plan();

// ---- packed f32x2 math (sm_103a; ptxas never emits these from C++) ----
__device__ __forceinline__ ull mul2(ull a, ull b) {
  ull r;
  asm("mul.rn.f32x2 %0, %1, %2;" : "=l"(r) : "l"(a), "l"(b));
  return r;
}
__device__ __forceinline__ void fma2(ull& d, ull a, ull b) {
  asm("fma.rn.f32x2 %0, %1, %2, %3;" : "=l"(d) : "l"(a), "l"(b), "l"(d));
}

// All PLAN reads below appear ONLY in template-argument position.

template<int OFF>
__device__ __forceinline__ ull ldcg(const ull* __restrict__ scg) {
  return scg[OFF];                         // LDS.64 [scg + literal]
}

template<int FIRST, int A, int B2, int SEGR>
__device__ __forceinline__ void step(ull* __restrict__ acc,
                                     const ull* __restrict__ x1r,
                                     const ull* __restrict__ x2r,
                                     ull& p, ull cgv) {
  if constexpr (FIRST) p = mul2(x1r[A], x2r[B2]);
  fma2(acc[SEGR], cgv, p);
}

template<int MLO, int J0, int... K>
__device__ __forceinline__ void run_chunk(ull* __restrict__ acc,
                                          const ull* __restrict__ x1r,
                                          const ull* __restrict__ x2r,
                                          const ull* __restrict__ scg,
                                          ull& p,
                                          std::integer_sequence<int, K...>) {
  ull cgv[sizeof...(K)];
  ( (cgv[K] = ldcg<PLAN.fcgi[J0 + K]>(scg)), ... );   // independent LDS batch
  ( step<PLAN.ffirst[J0 + K], PLAN.fm1[J0 + K], PLAN.fm2[J0 + K],
         PLAN.fseg[J0 + K] - MLO>(acc, x1r, x2r, p, cgv[K]), ... );
}

template<int MLO, int FB, int FE, int... C>
__device__ __forceinline__ void run_chunks(ull* __restrict__ acc,
                                           const ull* __restrict__ x1r,
                                           const ull* __restrict__ x2r,
                                           const ull* __restrict__ scg,
                                           std::integer_sequence<int, C...>) {
  ull p = 0;
  ( run_chunk<MLO, FB + C * CHUNK>(
        acc, x1r, x2r, scg, p,
        std::make_integer_sequence<int,
            ((FE - (FB + C * CHUNK)) < CHUNK ? (FE - (FB + C * CHUNK)) : CHUNK)>{}),
    ... );
}

template<unsigned MASK, int M>
__device__ __forceinline__ void load1(ull* __restrict__ r,
                                      const ull* __restrict__ src, int c) {
  if constexpr ((MASK >> M) & 1u) r[M] = src[M * NCU + c];
}
template<unsigned MASK, int... M>
__device__ __forceinline__ void loadm(ull* __restrict__ r,
                                      const ull* __restrict__ src, int c,
                                      std::integer_sequence<int, M...>) {
  ( load1<MASK, M>(r, src, c), ... );
}

template<int MLO, int... S>
__device__ __forceinline__ void storem(ull* __restrict__ outu,
                                       const ull* __restrict__ acc, int c,
                                       std::integer_sequence<int, S...>) {
  ( (outu[(MLO + S) * NCU + c] = acc[S]), ... );
}

template<int MLO, int MHI, int FB, int FE, unsigned U1, unsigned U2>
__device__ __forceinline__ void rg(const ull* __restrict__ x1u,
                                   const ull* __restrict__ x2u,
                                   ull* __restrict__ outu,
                                   const ull* __restrict__ scg, int c) {
  ull x1r[NM], x2r[NM];
  loadm<U1>(x1r, x1u, c, std::make_integer_sequence<int, NM>{});
  loadm<U2>(x2r, x2u, c, std::make_integer_sequence<int, NM>{});
  ull acc[MHI - MLO] = {};
  run_chunks<MLO, FB, FE>(
      acc, x1r, x2r, scg,
      std::make_integer_sequence<int, (FE - FB + CHUNK - 1) / CHUNK>{});
  storem<MLO>(outu, acc, c, std::make_integer_sequence<int, MHI - MLO>{});
}

template<int G>
__device__ __forceinline__ void rung(const ull* __restrict__ x1u,
                                     const ull* __restrict__ x2u,
                                     ull* __restrict__ outu,
                                     const ull* __restrict__ scg, int c) {
  rg<PLAN.mlo[G], PLAN.mhi[G], PLAN.fb[G], PLAN.fb[G + 1],
     PLAN.u1[G], PLAN.u2[G]>(x1u, x2u, outu, scg, c);
}

// 512 threads = 16 warps = 8 groups x 2 channel-halves; grid = 128 -> exactly
// one CTA per SM (single uniform wave), 128-reg budget per thread.
__global__ void __launch_bounds__(512, 1)
tp_kernel(const float* __restrict__ x1, const float* __restrict__ x2,
          const float* __restrict__ cg, float* __restrict__ out) {
  __shared__ __align__(16) ull scg[NNZ];   // cg duplicated into both f32x2 lanes
  const int tid = threadIdx.x;
  for (int i = tid; i < NNZ; i += 512) {
    ull u = (ull)__float_as_uint(__ldg(cg + i));
    scg[i] = u | (u << 32);
  }
  __syncthreads();

  const int b   = blockIdx.x;
  const int wid = tid >> 5;
  const int g   = wid & 7;                 // segment group
  const int h   = wid >> 3;                // channel half
  const int c   = h * 32 + (tid & 31);     // f32x2 lane index within row

  const ull* x1u = reinterpret_cast<const ull*>(x1) + b * (NM * NCU);
  const ull* x2u = reinterpret_cast<const ull*>(x2) + b * (NM * NCU);
  ull*       ou  = reinterpret_cast<ull*>(out)      + b * (NM * NCU);

  switch (g) {
    case 0: rung<0>(x1u, x2u, ou, scg, c); break;
    case 1: rung<1>(x1u, x2u, ou, scg, c); break;
    case 2: rung<2>(x1u, x2u, ou, scg, c); break;
    case 3: rung<3>(x1u, x2u, ou, scg, c); break;
    case 4: rung<4>(x1u, x2u, ou, scg, c); break;
    case 5: rung<5>(x1u, x2u, ou, scg, c); break;
    case 6: rung<6>(x1u, x2u, ou, scg, c); break;
    case 7: rung<7>(x1u, x2u, ou, scg, c); break;
  }
}

// ---- generic fallback (only if runtime nnz != compile-time NNZ) ----
__global__ void tp_generic(const float* __restrict__ x1, const float* __restrict__ x2,
                           const float* __restrict__ cg,
                           const int* __restrict__ M1, const int* __restrict__ M2,
                           const int* __restrict__ seg, int nnz,
                           float* __restrict__ out) {
  const int b = blockIdx.x;
  const int c = threadIdx.x;
  const float* x1b = x1 + b * NM * NC;
  const float* x2b = x2 + b * NM * NC;
  float acc = 0.f;
  int cur = seg[0];
  for (int i = 0; i < nnz; ++i) {
    int s = seg[i];
    if (s != cur) { out[(b * NM + cur) * NC + c] = acc; acc = 0.f; cur = s; }
    acc += cg[i] * x1b[M1[i] * NC + c] * x2b[M2[i] * NC + c];
  }
  out[(b * NM + cur) * NC + c] = acc;
}

}  // namespace tp

extern "C" void kernel_launch(void* const* d_in, const int* in_sizes, int n_in,
                              void* d_out, int out_size) {
  const float* x1 = (const float*)d_in[0];
  const float* x2 = (const float*)d_in[1];
  const float* cg = (const float*)d_in[2];
  const int*   M1 = (const int*)  d_in[3];
  const int*   M2 = (const int*)  d_in[4];
  const int*   sg = (const int*)  d_in[5];
  float* out = (float*)d_out;

  if (in_sizes[2] == tp::NNZ) {
    tp::tp_kernel<<<tp::NB, 512>>>(x1, x2, cg, out);
  } else {
    // pattern mismatch safety net: zero then generic runtime-indexed kernel
    cudaMemsetAsync(d_out, 0, (size_t)out_size * sizeof(float));
    tp::tp_generic<<<tp::NB, tp::NC>>>(x1, x2, cg, M1, M2, sg, in_sizes[2], out);
  }
}